// round 6
// baseline (speedup 1.0000x reference)
#include <cuda_runtime.h>

// SeqSelfAttention (Bahdanau additive, windowed) — GB300 sm_103a
// B=4, L=1024, D=128, U=32, WIDTH=64, EPS=1e-7
//
// Algebra: window-max softmax shift only perturbs the +1e-7 denominator by
// exp(Mw-Mfull) (rel err <~1e-6); ba cancels exactly.
// R6: split-KV — each query-pair's 64-key window split across 2 warps
// (flash-style exact (m,s) merge). 16 warps/block doubles occupancy while
// keeping the 2-queries/warp shared-xv AV. qk: 256 blocks (no idle SMs),
// interleaved (Wt,Wx) float2 loads.

#define LSEQ 1024
#define BB   4
#define DD   128
#define UU   32
#define TI   16
#define CW   80   // TI + 64
#define NROWS (BB*LSEQ)

__device__ float g_q [NROWS*UU];
__device__ float g_kb[NROWS*UU];

__device__ __forceinline__ float fast_tanh(float x){
    float y; asm("tanh.approx.f32 %0, %1;" : "=f"(y) : "f"(x)); return y;
}

// ---------------------------------------------------------------------------
// Kernel 1: q = x @ Wt ; kb = x @ Wx + bh.  256 blocks x 256 thr,
// 16 rows/block, 2 rows/warp. W staged interleaved: wtx[d][u] = (Wt, Wx).
// ---------------------------------------------------------------------------
#define QK_RPB 16
__global__ __launch_bounds__(256) void qk_kernel(
        const float* __restrict__ x,
        const float* __restrict__ Wt,
        const float* __restrict__ Wx,
        const float* __restrict__ bh)
{
    __shared__ float xs [QK_RPB*DD];    // 8 KB
    __shared__ float wtx[DD*UU*2];      // 32 KB interleaved (Wt,Wx) pairs
    const int t    = threadIdx.x;
    const int row0 = blockIdx.x * QK_RPB;

    {   // stage
        const float4* xg = (const float4*)(x + row0*DD);
        float4* xs4 = (float4*)xs;
        xs4[t] = xg[t];  xs4[t+256] = xg[t+256];
        const float4* wtg = (const float4*)Wt;
        const float4* wxg = (const float4*)Wx;
        float2* wp = (float2*)wtx;
        #pragma unroll
        for (int i = 0; i < 4; i++){
            const int idx = t + i*256;          // f4 index into [128][32]
            const float4 a = wtg[idx];
            const float4 b = wxg[idx];
            wp[4*idx+0] = make_float2(a.x, b.x);
            wp[4*idx+1] = make_float2(a.y, b.y);
            wp[4*idx+2] = make_float2(a.z, b.z);
            wp[4*idx+3] = make_float2(a.w, b.w);
        }
    }
    __syncthreads();

    const int u  = t & 31;
    const int rg = t >> 5;
    const int r0 = rg * 2;                 // 2 rows per warp
    float aq0=0,aq1=0, ak0=0,ak1=0;
    const float4* xs4 = (const float4*)xs;
    const float2* wp  = (const float2*)wtx;

    #pragma unroll 8
    for (int d4 = 0; d4 < 32; d4++){
        const float2 w0 = wp[(d4*4+0)*32 + u];   // conflict-free LDS.64
        const float2 w1 = wp[(d4*4+1)*32 + u];
        const float2 w2 = wp[(d4*4+2)*32 + u];
        const float2 w3 = wp[(d4*4+3)*32 + u];
        const float4 x0 = xs4[(r0+0)*32 + d4];   // broadcast LDS.128
        const float4 x1 = xs4[(r0+1)*32 + d4];
        aq0 += x0.x*w0.x + x0.y*w1.x + x0.z*w2.x + x0.w*w3.x;
        aq1 += x1.x*w0.x + x1.y*w1.x + x1.z*w2.x + x1.w*w3.x;
        ak0 += x0.x*w0.y + x0.y*w1.y + x0.z*w2.y + x0.w*w3.y;
        ak1 += x1.x*w0.y + x1.y*w1.y + x1.z*w2.y + x1.w*w3.y;
    }
    const float bhv = bh[u];
    const int r = row0 + r0;
    g_q [(r+0)*UU+u] = aq0;      g_q [(r+1)*UU+u] = aq1;
    g_kb[(r+0)*UU+u] = ak0+bhv;  g_kb[(r+1)*UU+u] = ak1+bhv;
}

// ---------------------------------------------------------------------------
// Kernel 2: windowed attention, split-KV. grid (64, 4), 512 thr (16 warps).
// Warp w: pair p = w&7 (queries 2p, 2p+1), key-half h = w>>3.
// Warp handles 32 keys of the 64-key window; exact (m,s) merge via smem.
// smem: xs[80][128] | kbs[80][36] (pv overlay) | qs[16][32] | was[32]
//       | Pst[8][2][2][2] | Aw[16][66]
// ---------------------------------------------------------------------------
#define KBS  36
#define OFF_KBS  (CW*DD)                   // 10240
#define OFF_QS   (OFF_KBS + CW*KBS)        // 13120
#define OFF_WAS  (OFF_QS + TI*UU)          // 13632
#define OFF_PST  (OFF_WAS + UU)            // 13664
#define OFF_AW   (OFF_PST + 64)            // 13728
#define SMEM_FLOATS (OFF_AW + 16*66)       // 14784 floats = 59136 B

extern __shared__ float smem[];

__global__ __launch_bounds__(512) void attn_kernel(
        const float* __restrict__ x,
        const float* __restrict__ Wa,
        float* __restrict__ out)
{
    float* xs  = smem;
    float* kbs = smem + OFF_KBS;
    float* qs  = smem + OFF_QS;
    float* was = smem + OFF_WAS;
    float* Pst = smem + OFF_PST;
    float* Aw  = smem + OFF_AW;

    const int t    = threadIdx.x;
    const int i0   = blockIdx.x * TI;
    const int base = blockIdx.y * LSEQ;

    // ---- stage: xs[80][128] f4, kbs[80][36] f4, qs[16][32], was ----
    {
        float4* xs4 = (float4*)xs;
        const float4* xg4 = (const float4*)x;
        #pragma unroll
        for (int i = 0; i < 5; i++){
            const int idx = t + i*512;            // [0,2560) f4 of [80][32]
            const int c = idx >> 5, dq = idx & 31;
            const int j = i0 - 32 + c;
            float4 v = make_float4(0.f,0.f,0.f,0.f);
            if (j >= 0 && j < LSEQ) v = xg4[(base + j)*32 + dq];
            xs4[c*32 + dq] = v;
        }
        const float4* kg4 = (const float4*)g_kb;
        #pragma unroll
        for (int i = 0; i < 2; i++){
            const int idx = t + i*512;            // [0,640) f4 of [80][8]
            if (idx < 640){
                const int c = idx >> 3, u4 = idx & 7;
                const int j = i0 - 32 + c;
                float4 v = make_float4(0.f,0.f,0.f,0.f);
                if (j >= 0 && j < LSEQ) v = kg4[(base + j)*8 + u4];
                ((float4*)(kbs + c*KBS))[u4] = v;
            }
        }
        if (t < 128) ((float4*)qs)[t] = ((const float4*)(g_q + (base+i0)*UU))[t];
        if (t < 32) was[t] = Wa[t];
    }
    __syncthreads();

    const int w = t >> 5;
    const int l = t & 31;
    const int p = w & 7;               // query pair (queries 2p, 2p+1)
    const int h = w >> 3;              // key half
    const int c0 = 2*p + 32*h + l;     // q0's key row (tile coords)

    // ---- logits: e0 (q0, key c0), e1 (q1, key c0+1) ----
    float e0 = 0.f, e1 = 0.f;
    {
        const float4* q0p = (const float4*)(qs + 2*p*UU);
        const float4* q1p = q0p + 8;
        const float4* kAp = (const float4*)(kbs + c0*KBS);
        const float4* kBp = (const float4*)(kbs + (c0+1)*KBS);
        const float4* wap = (const float4*)was;
        #pragma unroll
        for (int u4 = 0; u4 < 8; u4++){
            const float4 wa = wap[u4];            // broadcast
            const float4 q0 = q0p[u4];            // broadcast
            const float4 q1 = q1p[u4];
            const float4 kA = kAp[u4];            // conflict-free LDS.128
            const float4 kB = kBp[u4];
            e0 += wa.x*fast_tanh(q0.x+kA.x) + wa.y*fast_tanh(q0.y+kA.y)
                + wa.z*fast_tanh(q0.z+kA.z) + wa.w*fast_tanh(q0.w+kA.w);
            e1 += wa.x*fast_tanh(q1.x+kB.x) + wa.y*fast_tanh(q1.y+kB.y)
                + wa.z*fast_tanh(q1.z+kB.z) + wa.w*fast_tanh(q1.w+kB.w);
        }
    }
    const int j0 = i0 - 32 + c0;                 // q0's key index
    const bool v0 = (j0 >= 0) && (j0 < LSEQ);
    const bool v1 = (j0+1 >= 0) && (j0+1 < LSEQ);
    if (!v0) e0 = -1e30f;
    if (!v1) e1 = -1e30f;

    // ---- partial softmax over this warp's 32 keys ----
    float m0 = e0, m1 = e1;
    #pragma unroll
    for (int o = 16; o; o >>= 1){
        m0 = fmaxf(m0, __shfl_xor_sync(0xffffffffu, m0, o));
        m1 = fmaxf(m1, __shfl_xor_sync(0xffffffffu, m1, o));
    }
    float w0 = v0 ? __expf(e0 - m0) : 0.f;       // explicit zero: handles
    float w1 = v1 ? __expf(e1 - m1) : 0.f;       // fully-masked halves
    float s0 = w0, s1 = w1;
    #pragma unroll
    for (int o = 16; o; o >>= 1){
        s0 += __shfl_xor_sync(0xffffffffu, s0, o);
        s1 += __shfl_xor_sync(0xffffffffu, s1, o);
    }
    if (l == 0){                                  // publish (m, s) per (p,q,h)
        float* ps = Pst + ((p*2 + 0)*2 + h)*2;
        ps[0] = m0; ps[1] = s0;
        ps = Pst + ((p*2 + 1)*2 + h)*2;
        ps[0] = m1; ps[1] = s1;
    }
    __syncthreads();

    // ---- merge with peer half (exact) ----
    float a0, a1;
    {
        const float* ps0 = Pst + ((p*2 + 0)*2 + (1-h))*2;
        const float* ps1 = Pst + ((p*2 + 1)*2 + (1-h))*2;
        const float mp0 = ps0[0], sp0 = ps0[1];
        const float mp1 = ps1[0], sp1 = ps1[1];
        const float M0 = fmaxf(m0, mp0);
        const float M1 = fmaxf(m1, mp1);
        const float f0 = __expf(m0 - M0);
        const float f1 = __expf(m1 - M1);
        const float S0 = s0*f0 + sp0*__expf(mp0 - M0);
        const float S1 = s1*f1 + sp1*__expf(mp1 - M1);
        a0 = w0 * (f0 / (S0 + 1e-7f));
        a1 = w1 * (f1 / (S1 + 1e-7f));
    }

    // ---- publish weights: warp-private 33-slot table (slot k = row rb+k) ----
    float* A = Aw + w*66;
    A[2*l] = a0;                   // q0 slots 0..31
    A[2*(l+1) + 1] = a1;           // q1 slots 1..32
    if (l == 0){ A[1] = 0.f; A[64] = 0.f; }
    __syncwarp();

    // ---- partial AV over this warp's 33-row span (xv shared by q0,q1) ----
    float4 acc0 = make_float4(0.f,0.f,0.f,0.f);
    float4 acc1 = make_float4(0.f,0.f,0.f,0.f);
    {
        const int rb = 2*p + 32*h;
        const float4* xs4 = (const float4*)xs;
        const float2* A2  = (const float2*)A;
        #pragma unroll 11
        for (int k = 0; k < 33; k++){
            const float2 ab = A2[k];                 // broadcast LDS.64
            const float4 xv = xs4[(rb + k)*32 + l];  // conflict-free LDS.128
            acc0.x += ab.x*xv.x; acc0.y += ab.x*xv.y;
            acc0.z += ab.x*xv.z; acc0.w += ab.x*xv.w;
            acc1.x += ab.y*xv.x; acc1.y += ab.y*xv.y;
            acc1.z += ab.y*xv.z; acc1.w += ab.y*xv.w;
        }
    }

    // ---- merge halves (pv overlays kbs — dead after logits) ----
    float4* pv4 = (float4*)kbs;
    if (h == 1){
        pv4[(2*p    )*32 + l] = acc0;
        pv4[(2*p + 1)*32 + l] = acc1;
    }
    __syncthreads();
    if (h == 0){
        const float4 b0 = pv4[(2*p    )*32 + l];
        const float4 b1 = pv4[(2*p + 1)*32 + l];
        acc0.x += b0.x; acc0.y += b0.y; acc0.z += b0.z; acc0.w += b0.w;
        acc1.x += b1.x; acc1.y += b1.y; acc1.z += b1.z; acc1.w += b1.w;
        float4* out4 = (float4*)out;
        out4[(base + i0 + 2*p    )*32 + l] = acc0;
        out4[(base + i0 + 2*p + 1)*32 + l] = acc1;
    }
}

// ---------------------------------------------------------------------------
extern "C" void kernel_launch(void* const* d_in, const int* in_sizes, int n_in,
                              void* d_out, int out_size)
{
    const float* x  = (const float*)d_in[0];
    const float* Wt = (const float*)d_in[1];
    const float* Wx = (const float*)d_in[2];
    const float* bh = (const float*)d_in[3];
    const float* Wa = (const float*)d_in[4];
    // d_in[5] = ba : cancels exactly in the shifted softmax -> unused
    float* out = (float*)d_out;

    qk_kernel<<<NROWS/QK_RPB, 256>>>(x, Wt, Wx, bh);

    cudaFuncSetAttribute(attn_kernel,
                         cudaFuncAttributeMaxDynamicSharedMemorySize,
                         SMEM_FLOATS*4 + 256);
    dim3 grid(LSEQ/TI, BB);
    attn_kernel<<<grid, 512, SMEM_FLOATS*4>>>(x, Wa, out);
}

// round 7
// speedup vs baseline: 1.0585x; 1.0585x over previous
#include <cuda_runtime.h>

// SeqSelfAttention (Bahdanau additive, windowed) — GB300 sm_103a
// B=4, L=1024, D=128, U=32, WIDTH=64, EPS=1e-7
//
// Algebra: window-max softmax shift only perturbs the +1e-7 denominator by
// exp(Mw-Mfull) (rel err <~1e-6); ba cancels exactly.
// R7: R5 skeleton; logit phase re-shares kb rows between the two queries of
// a warp (q1 window = kA rows(l>=1) + kB rows + one orphan row handled by a
// u-parallel warp reduction) -> 5 LDS.128/iter instead of 7, float2 weight
// publish. qk = R5 verbatim.

#define LSEQ 1024
#define BB   4
#define DD   128
#define UU   32
#define TI   16
#define CW   80   // TI + 64
#define NROWS (BB*LSEQ)

__device__ float g_q [NROWS*UU];
__device__ float g_kb[NROWS*UU];

__device__ __forceinline__ float fast_tanh(float x){
    float y; asm("tanh.approx.f32 %0, %1;" : "=f"(y) : "f"(x)); return y;
}

// ---------------------------------------------------------------------------
// Kernel 1: q = x @ Wt ; kb = x @ Wx + bh.  128 blocks x 256 thr, 32 rows,
// 4 rows/warp. W in natural [d][u] layout (f4-coalesced stage, conflict-free
// scalar reads: lane = u).   (R5 verbatim — measured good.)
// ---------------------------------------------------------------------------
#define QK_RPB 32
__global__ __launch_bounds__(256) void qk_kernel(
        const float* __restrict__ x,
        const float* __restrict__ Wt,
        const float* __restrict__ Wx,
        const float* __restrict__ bh)
{
    __shared__ float xs [QK_RPB*DD];    // 16 KB
    __shared__ float wts[DD*UU];        // 16 KB  [d][u]
    __shared__ float wxs[DD*UU];        // 16 KB
    const int t    = threadIdx.x;
    const int row0 = blockIdx.x * QK_RPB;

    {   // stage (all coalesced float4, layout-preserving)
        const float4* xg = (const float4*)(x + row0*DD);
        float4* xs4 = (float4*)xs;
        const float4* wtg = (const float4*)Wt; float4* wt4 = (float4*)wts;
        const float4* wxg = (const float4*)Wx; float4* wx4 = (float4*)wxs;
        #pragma unroll
        for (int i = 0; i < 4; i++){
            xs4[t + i*256] = xg [t + i*256];
            wt4[t + i*256] = wtg[t + i*256];
            wx4[t + i*256] = wxg[t + i*256];
        }
    }
    __syncthreads();

    const int u  = t & 31;
    const int rg = t >> 5;
    const int rb = rg * 4;                 // 4 rows per warp
    float aq0=0,aq1=0,aq2=0,aq3=0, ak0=0,ak1=0,ak2=0,ak3=0;
    const float4* xs4 = (const float4*)xs;

    #pragma unroll 8
    for (int d4 = 0; d4 < 32; d4++){
        const int db = d4*4*32 + u;
        const float wt0 = wts[db], wt1 = wts[db+32], wt2 = wts[db+64], wt3 = wts[db+96];
        const float wx0 = wxs[db], wx1 = wxs[db+32], wx2 = wxs[db+64], wx3 = wxs[db+96];
        const float4 x0 = xs4[(rb+0)*32 + d4];   // broadcast LDS.128
        const float4 x1 = xs4[(rb+1)*32 + d4];
        const float4 x2 = xs4[(rb+2)*32 + d4];
        const float4 x3 = xs4[(rb+3)*32 + d4];
        aq0 += x0.x*wt0 + x0.y*wt1 + x0.z*wt2 + x0.w*wt3;
        aq1 += x1.x*wt0 + x1.y*wt1 + x1.z*wt2 + x1.w*wt3;
        aq2 += x2.x*wt0 + x2.y*wt1 + x2.z*wt2 + x2.w*wt3;
        aq3 += x3.x*wt0 + x3.y*wt1 + x3.z*wt2 + x3.w*wt3;
        ak0 += x0.x*wx0 + x0.y*wx1 + x0.z*wx2 + x0.w*wx3;
        ak1 += x1.x*wx0 + x1.y*wx1 + x1.z*wx2 + x1.w*wx3;
        ak2 += x2.x*wx0 + x2.y*wx1 + x2.z*wx2 + x2.w*wx3;
        ak3 += x3.x*wx0 + x3.y*wx1 + x3.z*wx2 + x3.w*wx3;
    }
    const float bhv = bh[u];
    const int r = row0 + rb;
    g_q [(r+0)*UU+u] = aq0;      g_q [(r+1)*UU+u] = aq1;
    g_q [(r+2)*UU+u] = aq2;      g_q [(r+3)*UU+u] = aq3;
    g_kb[(r+0)*UU+u] = ak0+bhv;  g_kb[(r+1)*UU+u] = ak1+bhv;
    g_kb[(r+2)*UU+u] = ak2+bhv;  g_kb[(r+3)*UU+u] = ak3+bhv;
}

// ---------------------------------------------------------------------------
// Kernel 2: windowed attention. grid (L/16, B) = 256 blocks, 256 thr.
// Warp w owns queries 2w, 2w+1. Lane l loads kb rows c0=2w+l, c1=c0+32 ONCE;
// both queries' logits come from those registers. q1's window additionally
// needs row 2w+64 (orphan): u-parallel warp reduction, folded into softmax.
// smem: xs[80][128] | kbs[80][36] | qs[16][32] | was[32] | Aw[8][132]
// ---------------------------------------------------------------------------
#define KBS  36
#define OFF_KBS  (CW*DD)                   // 10240
#define OFF_QS   (OFF_KBS + CW*KBS)        // 13120
#define OFF_WAS  (OFF_QS + TI*UU)          // 13632
#define OFF_AW   (OFF_WAS + UU)            // 13664
#define SMEM_FLOATS (OFF_AW + 8*132)       // 14720 floats = 58880 B

extern __shared__ float smem[];

__global__ __launch_bounds__(256) void attn_kernel(
        const float* __restrict__ x,
        const float* __restrict__ Wa,
        float* __restrict__ out)
{
    float* xs  = smem;
    float* kbs = smem + OFF_KBS;
    float* qs  = smem + OFF_QS;
    float* was = smem + OFF_WAS;
    float* Aw  = smem + OFF_AW;

    const int t    = threadIdx.x;
    const int i0   = blockIdx.x * TI;
    const int base = blockIdx.y * LSEQ;

    // ---- stage: xs[80][128] f4, kbs[80][36] f4, qs[16][32], was ----
    {
        float4* xs4 = (float4*)xs;
        const float4* xg4 = (const float4*)x;
        #pragma unroll
        for (int i = 0; i < 10; i++){
            const int idx = t + i*256;            // [0,2560) f4 of [80][32]
            const int c = idx >> 5, dq = idx & 31;
            const int j = i0 - 32 + c;
            float4 v = make_float4(0.f,0.f,0.f,0.f);
            if (j >= 0 && j < LSEQ) v = xg4[(base + j)*32 + dq];
            xs4[c*32 + dq] = v;
        }
        const float4* kg4 = (const float4*)g_kb;
        #pragma unroll
        for (int i = 0; i < 3; i++){
            const int idx = t + i*256;            // [0,640) f4 of [80][8]
            if (idx < 640){
                const int c = idx >> 3, u4 = idx & 7;
                const int j = i0 - 32 + c;
                float4 v = make_float4(0.f,0.f,0.f,0.f);
                if (j >= 0 && j < LSEQ) v = kg4[(base + j)*8 + u4];
                ((float4*)(kbs + c*KBS))[u4] = v;
            }
        }
        if (t < 128) ((float4*)qs)[t] = ((const float4*)(g_q + (base+i0)*UU))[t];
        if (t < 32) was[t] = Wa[t];
    }
    __syncthreads();

    const int w = t >> 5;
    const int l = t & 31;
    const int c0 = 2*w + l, c1 = c0 + 32;

    // ---- logits: kA/kB rows loaded once, shared by q0 and q1 ----
    // q0 (query 2w):   window rows [2w, 2w+63]  = kA(all) + kB(all)
    // q1 (query 2w+1): window rows [2w+1,2w+64] = kA(l>=1) + kB(all) + orphan
    float e0a = 0.f, e0b = 0.f, e1a = 0.f, e1b = 0.f;
    {
        const float4* q0p = (const float4*)(qs + 2*w*UU);
        const float4* q1p = q0p + 8;
        const float4* kAp = (const float4*)(kbs + c0*KBS);
        const float4* kBp = (const float4*)(kbs + c1*KBS);
        const float4* wap = (const float4*)was;
        #pragma unroll
        for (int u4 = 0; u4 < 8; u4++){
            const float4 wa = wap[u4];            // broadcast
            const float4 q0 = q0p[u4];            // broadcast
            const float4 q1 = q1p[u4];
            const float4 kA = kAp[u4];            // conflict-free LDS.128
            const float4 kB = kBp[u4];
            e0a += wa.x*fast_tanh(q0.x+kA.x) + wa.y*fast_tanh(q0.y+kA.y)
                 + wa.z*fast_tanh(q0.z+kA.z) + wa.w*fast_tanh(q0.w+kA.w);
            e0b += wa.x*fast_tanh(q0.x+kB.x) + wa.y*fast_tanh(q0.y+kB.y)
                 + wa.z*fast_tanh(q0.z+kB.z) + wa.w*fast_tanh(q0.w+kB.w);
            e1a += wa.x*fast_tanh(q1.x+kA.x) + wa.y*fast_tanh(q1.y+kA.y)
                 + wa.z*fast_tanh(q1.z+kA.z) + wa.w*fast_tanh(q1.w+kA.w);
            e1b += wa.x*fast_tanh(q1.x+kB.x) + wa.y*fast_tanh(q1.y+kB.y)
                 + wa.z*fast_tanh(q1.z+kB.z) + wa.w*fast_tanh(q1.w+kB.w);
        }
    }

    // ---- orphan row 2w+64 for q1: u-parallel (lane = unit) ----
    float eo;
    {
        const float pv = was[l] * fast_tanh(qs[(2*w+1)*UU + l]
                                          + kbs[(2*w+64)*KBS + l]);
        eo = pv;
        #pragma unroll
        for (int o = 16; o; o >>= 1) eo += __shfl_xor_sync(0xffffffffu, eo, o);
        if (i0 + 2*w + 32 >= LSEQ) eo = -1e30f;   // warp-uniform mask
    }

    // ---- masks ----
    {
        const int j0 = i0 - 32 + c0;              // kA row's key index
        if (j0 < 0){ e0a = -1e30f; e1a = -1e30f; }
        if (j0 + 32 >= LSEQ){ e0b = -1e30f; e1b = -1e30f; }
        if (l == 0) e1a = -1e30f;                 // row 2w not in q1 window
    }

    // ---- two warp softmaxes (q1 includes orphan term) ----
    float a0a, a0b, a1a, a1b, ao;
    {
        float m0 = fmaxf(e0a, e0b), m1 = fmaxf(e1a, e1b);
        #pragma unroll
        for (int o = 16; o; o >>= 1){
            m0 = fmaxf(m0, __shfl_xor_sync(0xffffffffu, m0, o));
            m1 = fmaxf(m1, __shfl_xor_sync(0xffffffffu, m1, o));
        }
        const float M1 = fmaxf(m1, eo);
        const float w0a = __expf(e0a - m0), w0b = __expf(e0b - m0);
        const float w1a = __expf(e1a - M1), w1b = __expf(e1b - M1);
        float s0 = w0a + w0b, s1 = w1a + w1b;
        #pragma unroll
        for (int o = 16; o; o >>= 1){
            s0 += __shfl_xor_sync(0xffffffffu, s0, o);
            s1 += __shfl_xor_sync(0xffffffffu, s1, o);
        }
        const float wo = __expf(eo - M1);         // warp-uniform
        const float inv0 = 1.f / (s0 + 1e-7f);
        const float inv1 = 1.f / ((s1 + wo) + 1e-7f);
        a0a = w0a*inv0; a0b = w0b*inv0;
        a1a = w1a*inv1; a1b = w1b*inv1; ao = wo*inv1;
    }

    // ---- publish: slot k <-> row 2w+k ; (.x=q0, .y=q1), float2 stores ----
    float* A = Aw + w*132;
    ((float2*)A)[l]      = make_float2(a0a, a1a);   // slots 0..31
    ((float2*)A)[l + 32] = make_float2(a0b, a1b);   // slots 32..63
    if (l == 0) ((float2*)A)[64] = make_float2(0.f, ao);   // orphan slot
    __syncwarp();

    // ---- AV: one xv read feeds both queries ----
    {
        const float4* xs4 = (const float4*)xs;
        const float2* A2  = (const float2*)A;
        float4 acc0 = make_float4(0.f,0.f,0.f,0.f);
        float4 acc1 = make_float4(0.f,0.f,0.f,0.f);
        #pragma unroll 13
        for (int k = 0; k <= 64; k++){
            const float2 ab = A2[k];                 // broadcast LDS.64
            const float4 xv = xs4[(2*w + k)*32 + l]; // conflict-free LDS.128
            acc0.x += ab.x*xv.x; acc0.y += ab.x*xv.y;
            acc0.z += ab.x*xv.z; acc0.w += ab.x*xv.w;
            acc1.x += ab.y*xv.x; acc1.y += ab.y*xv.y;
            acc1.z += ab.y*xv.z; acc1.w += ab.y*xv.w;
        }
        float4* out4 = (float4*)out;
        out4[(base + i0 + 2*w    )*32 + l] = acc0;
        out4[(base + i0 + 2*w + 1)*32 + l] = acc1;
    }
}

// ---------------------------------------------------------------------------
extern "C" void kernel_launch(void* const* d_in, const int* in_sizes, int n_in,
                              void* d_out, int out_size)
{
    const float* x  = (const float*)d_in[0];
    const float* Wt = (const float*)d_in[1];
    const float* Wx = (const float*)d_in[2];
    const float* bh = (const float*)d_in[3];
    const float* Wa = (const float*)d_in[4];
    // d_in[5] = ba : cancels exactly in the shifted softmax -> unused
    float* out = (float*)d_out;

    qk_kernel<<<NROWS/QK_RPB, 256>>>(x, Wt, Wx, bh);

    cudaFuncSetAttribute(attn_kernel,
                         cudaFuncAttributeMaxDynamicSharedMemorySize,
                         SMEM_FLOATS*4 + 256);
    dim3 grid(LSEQ/TI, BB);
    attn_kernel<<<grid, 256, SMEM_FLOATS*4>>>(x, Wa, out);
}